// round 11
// baseline (speedup 1.0000x reference)
#include <cuda_runtime.h>
#include <cuda_fp16.h>
#include <cstdint>

#define BB    4
#define TT    2048
#define DM    1024
#define HQ    16
#define HKV   4
#define HD    64
#define MROWS (BB*TT)

#define SCQ 0.1803368801111204f         // 0.125 * log2(e)

// fp16 scratch (device globals)
__device__ __half g_xh  [MROWS*DM];
__device__ __half g_wqt [DM*DM];            // Wq^T  [n][k]
__device__ __half g_wkvt[(2*HKV*HD)*DM];    // Wkv^T [n][k]
__device__ __half g_wot [DM*DM];            // Wo^T  [n][k]
__device__ __half g_qh  [BB*HQ *TT*HD];     // (b*HQ+h, t, d), pre-scaled SCQ
__device__ __half g_kh  [BB*HKV*TT*HD];     // (b*HKV+hk, t, d)
__device__ __half g_vth [BB*HKV*HD*TT];     // (b*HKV+hk, d, t)
__device__ __half g_aoh [BB*TT*DM];         // (b, t, h*64+d)

// ---------------------------------------------------------------------------
__device__ __forceinline__ float ex2(float x) {
    float r; asm("ex2.approx.f32 %0, %1;" : "=f"(r) : "f"(x)); return r;
}
__device__ __forceinline__ uint32_t ex2h2(uint32_t x) {
    uint32_t r; asm("ex2.approx.f16x2 %0, %1;" : "=r"(r) : "r"(x)); return r;
}
__device__ __forceinline__ uint32_t smem_u32(const void* p) {
    return (uint32_t)__cvta_generic_to_shared(p);
}
__device__ __forceinline__ void cpa16(uint32_t dst, const void* src) {
    asm volatile("cp.async.cg.shared.global [%0], [%1], 16;"
                 :: "r"(dst), "l"(src));
}
#define CP_COMMIT() asm volatile("cp.async.commit_group;" ::: "memory")
#define CP_WAIT1()  asm volatile("cp.async.wait_group 1;" ::: "memory")
#define CP_WAIT0()  asm volatile("cp.async.wait_group 0;" ::: "memory")

__device__ __forceinline__ void ldm4(uint32_t* r, uint32_t addr) {
    asm volatile("ldmatrix.sync.aligned.m8n8.x4.shared.b16 {%0,%1,%2,%3}, [%4];"
                 : "=r"(r[0]), "=r"(r[1]), "=r"(r[2]), "=r"(r[3]) : "r"(addr));
}
__device__ __forceinline__ void mma16(float* d, const uint32_t* a, const uint32_t* b) {
    asm volatile(
        "mma.sync.aligned.m16n8k16.row.col.f32.f16.f16.f32 "
        "{%0,%1,%2,%3}, {%4,%5,%6,%7}, {%8,%9}, {%0,%1,%2,%3};"
        : "+f"(d[0]), "+f"(d[1]), "+f"(d[2]), "+f"(d[3])
        : "r"(a[0]), "r"(a[1]), "r"(a[2]), "r"(a[3]), "r"(b[0]), "r"(b[1]));
}
__device__ __forceinline__ uint32_t packh2(float a, float b) {
    __half2 h = __floats2half2_rn(a, b);
    return *(uint32_t*)&h;
}

// ---------------------------------------------------------------------------
// Prep kernels
// ---------------------------------------------------------------------------
__global__ __launch_bounds__(256)
void cvt_fp16(const float* __restrict__ src, __half* __restrict__ dst, int n)
{
    int i = (blockIdx.x * 256 + threadIdx.x) * 4;
    if (i < n) {
        float4 v = *(const float4*)(src + i);
        uint2 o = {packh2(v.x, v.y), packh2(v.z, v.w)};
        *(uint2*)(dst + i) = o;
    }
}

// All three W transposes in one launch. blockIdx.z: 0=Wq, 1=Wkv, 2=Wo.
__global__ __launch_bounds__(256)
void trW3(const float* __restrict__ Wq, const float* __restrict__ Wkv,
          const float* __restrict__ Wo,
          __half* __restrict__ wqt, __half* __restrict__ wkvt,
          __half* __restrict__ wot)
{
    const float* W; __half* Wt; int N;
    if (blockIdx.z == 0)      { W = Wq;  Wt = wqt;  N = DM; }
    else if (blockIdx.z == 1) { W = Wkv; Wt = wkvt; N = 2 * HKV * HD; }
    else                      { W = Wo;  Wt = wot;  N = DM; }
    const int n0 = blockIdx.x * 32;
    if (n0 >= N) return;
    const int k0 = blockIdx.y * 32;

    __shared__ float tile[32][33];
#pragma unroll
    for (int i = threadIdx.y; i < 32; i += 8)
        tile[i][threadIdx.x] = W[(size_t)(k0 + i) * N + n0 + threadIdx.x];
    __syncthreads();
#pragma unroll
    for (int i = threadIdx.y; i < 32; i += 8)
        Wt[(size_t)(n0 + i) * DM + k0 + threadIdx.x] =
            __float2half(tile[threadIdx.x][i]);
}

// ---------------------------------------------------------------------------
// GEMM core: 128x128 tile, BK=64, 256 thr, 2(M)x4(N) warps, ldmatrix,
// 3-stage cp.async pipeline (steady-state wait_group 1).
// ---------------------------------------------------------------------------
#define GST 36                               // words per smem row (64h + pad)
#define GTW (128 * GST)                      // words per A-or-B tile stage
#define GEMM_SMEM ((6 * GTW) * 4)            // 3 stages x (A,B)

struct GemmCore {
    uint32_t smBase;
    const __half* A;
    const __half* Wt;
    int K, bm, bn, tid;
    int rselA, cselA, rselB, cselB, wm, wn;

    __device__ __forceinline__ void load_tile(int kt, int st) {
        const uint32_t ab = smBase + st * 2 * GTW * 4;
        const uint32_t bb = ab + GTW * 4;
#pragma unroll
        for (int i = 0; i < 4; i++) {
            int c = tid + i * 256;
            int rr = c >> 3, off = c & 7;
            cpa16(ab + rr * (GST * 4) + off * 16,
                  A + (size_t)(bm + rr) * K + kt + off * 8);
            cpa16(bb + rr * (GST * 4) + off * 16,
                  Wt + (size_t)(bn + rr) * K + kt + off * 8);
        }
    }

    __device__ __forceinline__ void run(float acc[4][4][4]) {
        load_tile(0, 0);  CP_COMMIT();
        load_tile(64, 1); CP_COMMIT();
        const int NIT = K / 64;
        for (int it = 0; it < NIT; it++) {
            if (it + 1 < NIT) CP_WAIT1(); else CP_WAIT0();
            __syncthreads();
            if (it + 2 < NIT) { load_tile((it + 2) * 64, (it + 2) % 3); CP_COMMIT(); }
            const int cur = it % 3;
            const uint32_t smAc = smBase + cur * 2 * GTW * 4;
            const uint32_t smBc = smAc + GTW * 4;
#pragma unroll
            for (int ks = 0; ks < 4; ks++) {
                uint32_t af[4][4];
#pragma unroll
                for (int mf = 0; mf < 4; mf++)
                    ldm4(af[mf], smAc + (wm * 64 + mf * 16 + rselA) * (GST * 4)
                                   + cselA + ks * 32);
#pragma unroll
                for (int nfp = 0; nfp < 4; nfp += 2) {
                    uint32_t bf[4];
                    ldm4(bf, smBc + (wn * 32 + nfp * 8 + rselB) * (GST * 4)
                               + cselB + ks * 32);
#pragma unroll
                    for (int mf = 0; mf < 4; mf++) {
                        mma16(acc[mf][nfp],     af[mf], bf);
                        mma16(acc[mf][nfp + 1], af[mf], bf + 2);
                    }
                }
            }
        }
    }
};

__device__ __forceinline__ void gemm_init(GemmCore& gc, const __half* A,
                                          const __half* Wt, int K, int bm,
                                          int bn, uint32_t smBase)
{
    const int tid = threadIdx.x, lane = tid & 31;
    gc.smBase = smBase; gc.A = A; gc.Wt = Wt; gc.K = K;
    gc.bm = bm; gc.bn = bn; gc.tid = tid;
    gc.wm = (tid >> 5) >> 2; gc.wn = (tid >> 5) & 3;
    gc.rselA = (lane & 7) + ((lane >> 3) & 1) * 8;
    gc.cselA = ((lane >> 4) & 1) * 16;
    gc.rselB = (lane & 7) + ((lane >> 4) & 1) * 8;
    gc.cselB = ((lane >> 3) & 1) * 16;
}

// ---------------------------------------------------------------------------
// Fused Q + KV projection. grid (12, 64): bx 0-7 -> Q tiles, 8-11 -> KV.
// ---------------------------------------------------------------------------
__global__ __launch_bounds__(256, 2)
void tcmm_qkv(const __half* __restrict__ A, const __half* __restrict__ wqt,
              const __half* __restrict__ wkvt,
              const float* __restrict__ cosb, const float* __restrict__ sinb)
{
    extern __shared__ __align__(16) uint32_t gsm[];
    const bool isQ = blockIdx.x < 8;
    const int  bn  = (isQ ? blockIdx.x : blockIdx.x - 8) * 128;
    const int  bm  = blockIdx.y * 128;

    GemmCore gc;
    gemm_init(gc, A, isQ ? wqt : wkvt, DM, bm, bn, smem_u32(gsm));

    float acc[4][4][4] = {};
    gc.run(acc);

    const int lane = threadIdx.x & 31, g = lane >> 2, t = lane & 3;
    const int wid  = threadIdx.x >> 5, wm = wid >> 2, wn = wid & 3;

#pragma unroll
    for (int mf = 0; mf < 4; mf++) {
#pragma unroll
        for (int half = 0; half < 2; half++) {
            const int r  = bm + wm * 64 + mf * 16 + g + half * 8;
            const int bq = r >> 11, tq = r & (TT - 1);
#pragma unroll
            for (int nf = 0; nf < 4; nf++) {
                const float v0 = acc[mf][nf][half * 2];
                const float v1 = acc[mf][nf][half * 2 + 1];
                const int col = bn + wn * 32 + nf * 8 + 2 * t;
                if (isQ) {
                    const int h = col >> 6, d = col & 63;
                    const float c  = cosb[tq * HD + d];
                    const float sn = sinb[tq * HD + d];
                    uint32_t p = packh2((v0 * c - v1 * sn) * SCQ,
                                        (v1 * c + v0 * sn) * SCQ);
                    *(uint32_t*)&g_qh[(((size_t)(bq * HQ + h) * TT + tq) << 6) + d] = p;
                } else {
                    const int hk = col >> 7, pair = (col >> 6) & 1, d = col & 63;
                    if (pair == 0) {
                        const float c  = cosb[tq * HD + d];
                        const float sn = sinb[tq * HD + d];
                        uint32_t p = packh2(v0 * c - v1 * sn, v1 * c + v0 * sn);
                        *(uint32_t*)&g_kh[(((size_t)(bq * HKV + hk) * TT + tq) << 6) + d] = p;
                    } else {
                        __half* dst = &g_vth[((size_t)(bq * HKV + hk) * HD + d) * TT + tq];
                        dst[0]  = __float2half(v0);
                        dst[TT] = __float2half(v1);
                    }
                }
            }
        }
    }
}

// ---------------------------------------------------------------------------
// Output projection: C = Ao @ Wo, plain fp32 store.
// ---------------------------------------------------------------------------
__global__ __launch_bounds__(256, 2)
void tcmm_o(const __half* __restrict__ A, const __half* __restrict__ Wt,
            float* __restrict__ C)
{
    extern __shared__ __align__(16) uint32_t gsm[];
    const int bm = blockIdx.y * 128, bn = blockIdx.x * 128;

    GemmCore gc;
    gemm_init(gc, A, Wt, DM, bm, bn, smem_u32(gsm));

    float acc[4][4][4] = {};
    gc.run(acc);

    const int lane = threadIdx.x & 31, g = lane >> 2, t = lane & 3;
    const int wid  = threadIdx.x >> 5, wm = wid >> 2, wn = wid & 3;

#pragma unroll
    for (int mf = 0; mf < 4; mf++)
#pragma unroll
        for (int half = 0; half < 2; half++) {
            const int r = bm + wm * 64 + mf * 16 + g + half * 8;
#pragma unroll
            for (int nf = 0; nf < 4; nf++) {
                const int col = bn + wn * 32 + nf * 8 + 2 * t;
                float2 o = {acc[mf][nf][half * 2], acc[mf][nf][half * 2 + 1]};
                *(float2*)(C + (size_t)r * DM + col) = o;
            }
        }
}

// ---------------------------------------------------------------------------
// Flash attention v2: mf=2 per warp (32 q-rows), 8 warps -> 256 q-rows/CTA.
// Each B-fragment ldmatrix feeds 4 MMAs -> smem read traffic halved per work.
// 1 CTA/SM (regs ~175). K-tile 64, 3-stage cp.async, P in registers.
// grid (BB*HQ, TT/256) = (64, 8).
// ---------------------------------------------------------------------------
#define AST 36
#define KTW (64 * AST)                  // words per K-or-V tile stage
#define ATTN_SMEM ((6 * KTW) * 4)       // 3 stages x (K,V)

__global__ __launch_bounds__(256, 1)
void attn_mma()
{
    extern __shared__ __align__(16) uint32_t dsm[];

    const int tid = threadIdx.x, lane = tid & 31, g = lane >> 2, t = lane & 3;
    const int bh  = blockIdx.x, b = bh >> 4, h = bh & 15, hk = h >> 2;
    const int qt  = blockIdx.y * 256;
    const int w   = tid >> 5;
    const int r0  = w * 32 + g;          // mf=0 base row; mf=1 adds 16

    const int rselB = (lane & 7) + ((lane >> 4) & 1) * 8;
    const int cselB = ((lane >> 3) & 1) * 16;

    const __half* Qb = g_qh  + (((size_t)bh * TT + qt) << 6);
    const __half* Kb = g_kh  + (((size_t)(b * HKV + hk) * TT) << 6);
    const __half* Vb = g_vth + ((size_t)(b * HKV + hk) * HD) * TT;

    // Q fragments for both mf halves (pre-scaled fp16 pairs)
    uint32_t qf[2][4][4];
#pragma unroll
    for (int mf = 0; mf < 2; mf++) {
        const int rr = r0 + mf * 16;
#pragma unroll
        for (int ks = 0; ks < 4; ks++) {
            qf[mf][ks][0] = *(const uint32_t*)(Qb + (size_t)rr * 64 + (ks * 8 + t) * 2);
            qf[mf][ks][1] = *(const uint32_t*)(Qb + (size_t)(rr + 8) * 64 + (ks * 8 + t) * 2);
            qf[mf][ks][2] = *(const uint32_t*)(Qb + (size_t)rr * 64 + (ks * 8 + t + 4) * 2);
            qf[mf][ks][3] = *(const uint32_t*)(Qb + (size_t)(rr + 8) * 64 + (ks * 8 + t + 4) * 2);
        }
    }

    const uint32_t smBase = smem_u32(dsm);

    auto load_tile = [&](int kt, int st) {
        const uint32_t kb = smBase + st * 2 * KTW * 4;
        const uint32_t vb = kb + KTW * 4;
#pragma unroll
        for (int i = 0; i < 2; i++) {
            int c = tid + i * 256;
            int rr = c >> 3, off = c & 7;
            cpa16(kb + rr * (AST * 4) + off * 16,
                  Kb + (size_t)(kt + rr) * 64 + off * 8);
            cpa16(vb + rr * (AST * 4) + off * 16,
                  Vb + (size_t)rr * TT + kt + off * 8);
        }
    };

    float o[2][8][4] = {};
    float m0[2] = {-3.0e38f, -3.0e38f}, m1[2] = {-3.0e38f, -3.0e38f};
    float l0[2] = {0.f, 0.f},           l1[2] = {0.f, 0.f};

    load_tile(0, 0);  CP_COMMIT();
    load_tile(64, 1); CP_COMMIT();

    const int NIT = TT / 64;
    for (int it = 0; it < NIT; it++) {
        if (it + 1 < NIT) CP_WAIT1(); else CP_WAIT0();
        __syncthreads();
        if (it + 2 < NIT) { load_tile((it + 2) * 64, (it + 2) % 3); CP_COMMIT(); }

        const int cur = it % 3;
        const uint32_t smKc = smBase + cur * 2 * KTW * 4;
        const uint32_t smVc = smKc + KTW * 4;

        // S = Q @ K^T for both mf halves (B fragment reused 4x)
        float s[2][8][4] = {};
#pragma unroll
        for (int nfp = 0; nfp < 8; nfp += 2) {
            const uint32_t ka = smKc + (nfp * 8 + rselB) * (AST * 4) + cselB;
#pragma unroll
            for (int ks = 0; ks < 4; ks++) {
                uint32_t bf[4];
                ldm4(bf, ka + ks * 32);
                mma16(s[0][nfp],     qf[0][ks], bf);
                mma16(s[0][nfp + 1], qf[0][ks], bf + 2);
                mma16(s[1][nfp],     qf[1][ks], bf);
                mma16(s[1][nfp + 1], qf[1][ks], bf + 2);
            }
        }

        // online softmax + P fragments, per mf half
        uint32_t af[2][4][4];
        float c0[2], c1[2];
#pragma unroll
        for (int mf = 0; mf < 2; mf++) {
            float tm0 = -3.0e38f, tm1 = -3.0e38f;
#pragma unroll
            for (int nf = 0; nf < 8; nf++) {
                tm0 = fmaxf(tm0, fmaxf(s[mf][nf][0], s[mf][nf][1]));
                tm1 = fmaxf(tm1, fmaxf(s[mf][nf][2], s[mf][nf][3]));
            }
            tm0 = fmaxf(tm0, __shfl_xor_sync(0xffffffffu, tm0, 1));
            tm0 = fmaxf(tm0, __shfl_xor_sync(0xffffffffu, tm0, 2));
            tm1 = fmaxf(tm1, __shfl_xor_sync(0xffffffffu, tm1, 1));
            tm1 = fmaxf(tm1, __shfl_xor_sync(0xffffffffu, tm1, 2));

            const float nm0 = fmaxf(m0[mf], tm0), nm1 = fmaxf(m1[mf], tm1);
            c0[mf] = ex2(m0[mf] - nm0);
            c1[mf] = ex2(m1[mf] - nm1);
            m0[mf] = nm0; m1[mf] = nm1;

            float lp0 = 0.f, lp1 = 0.f;
#pragma unroll
            for (int ks = 0; ks < 4; ks++) {
                const int lo = 2 * ks, hi = 2 * ks + 1;
                af[mf][ks][0] = ex2h2(packh2(s[mf][lo][0] - nm0, s[mf][lo][1] - nm0));
                af[mf][ks][1] = ex2h2(packh2(s[mf][lo][2] - nm1, s[mf][lo][3] - nm1));
                af[mf][ks][2] = ex2h2(packh2(s[mf][hi][0] - nm0, s[mf][hi][1] - nm0));
                af[mf][ks][3] = ex2h2(packh2(s[mf][hi][2] - nm1, s[mf][hi][3] - nm1));
                float2 f;
                f = __half22float2(*(__half2*)&af[mf][ks][0]); lp0 += f.x + f.y;
                f = __half22float2(*(__half2*)&af[mf][ks][2]); lp0 += f.x + f.y;
                f = __half22float2(*(__half2*)&af[mf][ks][1]); lp1 += f.x + f.y;
                f = __half22float2(*(__half2*)&af[mf][ks][3]); lp1 += f.x + f.y;
            }
            lp0 += __shfl_xor_sync(0xffffffffu, lp0, 1);
            lp0 += __shfl_xor_sync(0xffffffffu, lp0, 2);
            lp1 += __shfl_xor_sync(0xffffffffu, lp1, 1);
            lp1 += __shfl_xor_sync(0xffffffffu, lp1, 2);
            l0[mf] = l0[mf] * c0[mf] + lp0;
            l1[mf] = l1[mf] * c1[mf] + lp1;

#pragma unroll
            for (int nf = 0; nf < 8; nf++) {
                o[mf][nf][0] *= c0[mf]; o[mf][nf][1] *= c0[mf];
                o[mf][nf][2] *= c1[mf]; o[mf][nf][3] *= c1[mf];
            }
        }

        // O += P @ V (B fragment reused 4x)
#pragma unroll
        for (int nfp = 0; nfp < 8; nfp += 2) {
            const uint32_t va = smVc + (nfp * 8 + rselB) * (AST * 4) + cselB;
#pragma unroll
            for (int ks = 0; ks < 4; ks++) {
                uint32_t bf[4];
                ldm4(bf, va + ks * 32);
                mma16(o[0][nfp],     af[0][ks], bf);
                mma16(o[0][nfp + 1], af[0][ks], bf + 2);
                mma16(o[1][nfp],     af[1][ks], bf);
                mma16(o[1][nfp + 1], af[1][ks], bf + 2);
            }
        }
    }

#pragma unroll
    for (int mf = 0; mf < 2; mf++) {
        const float i0 = 1.f / l0[mf], i1 = 1.f / l1[mf];
        const int tr = qt + r0 + mf * 16;
#pragma unroll
        for (int nf = 0; nf < 8; nf++) {
            const int d = nf * 8 + 2 * t;
            *(uint32_t*)&g_aoh[((size_t)(b * TT + tr)     * DM) + h * 64 + d] =
                packh2(o[mf][nf][0] * i0, o[mf][nf][1] * i0);
            *(uint32_t*)&g_aoh[((size_t)(b * TT + tr + 8) * DM) + h * 64 + d] =
                packh2(o[mf][nf][2] * i1, o[mf][nf][3] * i1);
        }
    }
}

// ---------------------------------------------------------------------------
extern "C" void kernel_launch(void* const* d_in, const int* in_sizes, int n_in,
                              void* d_out, int out_size)
{
    const float* x    = (const float*)d_in[0];
    const float* cosb = (const float*)d_in[1];
    const float* sinb = (const float*)d_in[2];
    const float* Wq   = (const float*)d_in[3];
    const float* Wkv  = (const float*)d_in[4];
    const float* Wo   = (const float*)d_in[5];
    float* out = (float*)d_out;

    __half *p_xh = nullptr, *p_wqt = nullptr, *p_wkvt = nullptr,
           *p_wot = nullptr, *p_aoh = nullptr;
    cudaGetSymbolAddress((void**)&p_xh,  g_xh);
    cudaGetSymbolAddress((void**)&p_wqt, g_wqt);
    cudaGetSymbolAddress((void**)&p_wkvt,g_wkvt);
    cudaGetSymbolAddress((void**)&p_wot, g_wot);
    cudaGetSymbolAddress((void**)&p_aoh, g_aoh);

    cudaFuncSetAttribute(attn_mma, cudaFuncAttributeMaxDynamicSharedMemorySize,
                         ATTN_SMEM);
    cudaFuncSetAttribute(tcmm_qkv, cudaFuncAttributeMaxDynamicSharedMemorySize,
                         GEMM_SMEM);
    cudaFuncSetAttribute(tcmm_o, cudaFuncAttributeMaxDynamicSharedMemorySize,
                         GEMM_SMEM);

    // Prep: x -> fp16; all W -> transposed fp16 (single launch)
    cvt_fp16<<<(MROWS * DM) / (256 * 4), 256>>>(x, p_xh, MROWS * DM);
    {
        dim3 grid(DM / 32, DM / 32, 3), blk(32, 8);
        trW3<<<grid, blk>>>(Wq, Wkv, Wo, p_wqt, p_wkvt, p_wot);
    }

    {   // fused Q + KV projection (+RoPE, split, V transpose)
        dim3 grid(12, MROWS / 128);
        tcmm_qkv<<<grid, 256, GEMM_SMEM>>>(p_xh, p_wqt, p_wkvt, cosb, sinb);
    }
    {   // attention (256 q-rows per CTA)
        dim3 grid(BB * HQ, TT / 256);
        attn_mma<<<grid, 256, ATTN_SMEM>>>();
    }
    {   // output projection
        dim3 grid(DM / 128, MROWS / 128);
        tcmm_o<<<grid, 256, GEMM_SMEM>>>(p_aoh, p_wot, out);
    }
}

// round 12
// speedup vs baseline: 1.0823x; 1.0823x over previous
#include <cuda_runtime.h>
#include <cuda_fp16.h>
#include <cstdint>

#define BB    4
#define TT    2048
#define DM    1024
#define HQ    16
#define HKV   4
#define HD    64
#define MROWS (BB*TT)

#define SCQ 0.1803368801111204f         // 0.125 * log2(e)

// fp16 scratch (device globals)
__device__ __half g_xh  [MROWS*DM];
__device__ __half g_wqt [DM*DM];            // Wq^T  [n][k]
__device__ __half g_wkvt[(2*HKV*HD)*DM];    // Wkv^T [n][k]
__device__ __half g_wot [DM*DM];            // Wo^T  [n][k]
__device__ __half g_qh  [BB*HQ *TT*HD];     // (b*HQ+h, t, d), pre-scaled SCQ
__device__ __half g_kh  [BB*HKV*TT*HD];     // (b*HKV+hk, t, d)
__device__ __half g_vth [BB*HKV*HD*TT];     // (b*HKV+hk, d, t)
__device__ __half g_aoh [BB*TT*DM];         // (b, t, h*64+d)

// ---------------------------------------------------------------------------
__device__ __forceinline__ float ex2(float x) {
    float r; asm("ex2.approx.f32 %0, %1;" : "=f"(r) : "f"(x)); return r;
}
__device__ __forceinline__ uint32_t ex2h2(uint32_t x) {
    uint32_t r; asm("ex2.approx.f16x2 %0, %1;" : "=r"(r) : "r"(x)); return r;
}
__device__ __forceinline__ uint32_t smem_u32(const void* p) {
    return (uint32_t)__cvta_generic_to_shared(p);
}
__device__ __forceinline__ void cpa16(uint32_t dst, const void* src) {
    asm volatile("cp.async.cg.shared.global [%0], [%1], 16;"
                 :: "r"(dst), "l"(src));
}
#define CP_COMMIT() asm volatile("cp.async.commit_group;" ::: "memory")
#define CP_WAIT1()  asm volatile("cp.async.wait_group 1;" ::: "memory")
#define CP_WAIT0()  asm volatile("cp.async.wait_group 0;" ::: "memory")

__device__ __forceinline__ void ldm4(uint32_t* r, uint32_t addr) {
    asm volatile("ldmatrix.sync.aligned.m8n8.x4.shared.b16 {%0,%1,%2,%3}, [%4];"
                 : "=r"(r[0]), "=r"(r[1]), "=r"(r[2]), "=r"(r[3]) : "r"(addr));
}
__device__ __forceinline__ void mma16(float* d, const uint32_t* a, const uint32_t* b) {
    asm volatile(
        "mma.sync.aligned.m16n8k16.row.col.f32.f16.f16.f32 "
        "{%0,%1,%2,%3}, {%4,%5,%6,%7}, {%8,%9}, {%0,%1,%2,%3};"
        : "+f"(d[0]), "+f"(d[1]), "+f"(d[2]), "+f"(d[3])
        : "r"(a[0]), "r"(a[1]), "r"(a[2]), "r"(a[3]), "r"(b[0]), "r"(b[1]));
}
__device__ __forceinline__ uint32_t packh2(float a, float b) {
    __half2 h = __floats2half2_rn(a, b);
    return *(uint32_t*)&h;
}

// ---------------------------------------------------------------------------
// Prep kernels
// ---------------------------------------------------------------------------
__global__ __launch_bounds__(256)
void cvt_fp16(const float* __restrict__ src, __half* __restrict__ dst, int n)
{
    int i = (blockIdx.x * 256 + threadIdx.x) * 4;
    if (i < n) {
        float4 v = *(const float4*)(src + i);
        uint2 o = {packh2(v.x, v.y), packh2(v.z, v.w)};
        *(uint2*)(dst + i) = o;
    }
}

// All three W transposes in one launch. blockIdx.z: 0=Wq, 1=Wkv, 2=Wo.
__global__ __launch_bounds__(256)
void trW3(const float* __restrict__ Wq, const float* __restrict__ Wkv,
          const float* __restrict__ Wo,
          __half* __restrict__ wqt, __half* __restrict__ wkvt,
          __half* __restrict__ wot)
{
    const float* W; __half* Wt; int N;
    if (blockIdx.z == 0)      { W = Wq;  Wt = wqt;  N = DM; }
    else if (blockIdx.z == 1) { W = Wkv; Wt = wkvt; N = 2 * HKV * HD; }
    else                      { W = Wo;  Wt = wot;  N = DM; }
    const int n0 = blockIdx.x * 32;
    if (n0 >= N) return;
    const int k0 = blockIdx.y * 32;

    __shared__ float tile[32][33];
#pragma unroll
    for (int i = threadIdx.y; i < 32; i += 8)
        tile[i][threadIdx.x] = W[(size_t)(k0 + i) * N + n0 + threadIdx.x];
    __syncthreads();
#pragma unroll
    for (int i = threadIdx.y; i < 32; i += 8)
        Wt[(size_t)(n0 + i) * DM + k0 + threadIdx.x] =
            __float2half(tile[threadIdx.x][i]);
}

// ---------------------------------------------------------------------------
// GEMM core: 128x128 tile, BK=64, 256 thr, 2(M)x4(N) warps, ldmatrix,
// 3-stage cp.async pipeline (steady-state wait_group 1).
// ---------------------------------------------------------------------------
#define GST 36                               // words per smem row (64h + pad)
#define GTW (128 * GST)                      // words per A-or-B tile stage
#define GEMM_SMEM ((6 * GTW) * 4)            // 3 stages x (A,B)

struct GemmCore {
    uint32_t smBase;
    const __half* A;
    const __half* Wt;
    int K, bm, bn, tid;
    int rselA, cselA, rselB, cselB, wm, wn;

    __device__ __forceinline__ void load_tile(int kt, int st) {
        const uint32_t ab = smBase + st * 2 * GTW * 4;
        const uint32_t bb = ab + GTW * 4;
#pragma unroll
        for (int i = 0; i < 4; i++) {
            int c = tid + i * 256;
            int rr = c >> 3, off = c & 7;
            cpa16(ab + rr * (GST * 4) + off * 16,
                  A + (size_t)(bm + rr) * K + kt + off * 8);
            cpa16(bb + rr * (GST * 4) + off * 16,
                  Wt + (size_t)(bn + rr) * K + kt + off * 8);
        }
    }

    __device__ __forceinline__ void run(float acc[4][4][4]) {
        load_tile(0, 0);  CP_COMMIT();
        load_tile(64, 1); CP_COMMIT();
        const int NIT = K / 64;
        for (int it = 0; it < NIT; it++) {
            if (it + 1 < NIT) CP_WAIT1(); else CP_WAIT0();
            __syncthreads();
            if (it + 2 < NIT) { load_tile((it + 2) * 64, (it + 2) % 3); CP_COMMIT(); }
            const int cur = it % 3;
            const uint32_t smAc = smBase + cur * 2 * GTW * 4;
            const uint32_t smBc = smAc + GTW * 4;
#pragma unroll
            for (int ks = 0; ks < 4; ks++) {
                uint32_t af[4][4];
#pragma unroll
                for (int mf = 0; mf < 4; mf++)
                    ldm4(af[mf], smAc + (wm * 64 + mf * 16 + rselA) * (GST * 4)
                                   + cselA + ks * 32);
#pragma unroll
                for (int nfp = 0; nfp < 4; nfp += 2) {
                    uint32_t bf[4];
                    ldm4(bf, smBc + (wn * 32 + nfp * 8 + rselB) * (GST * 4)
                               + cselB + ks * 32);
#pragma unroll
                    for (int mf = 0; mf < 4; mf++) {
                        mma16(acc[mf][nfp],     af[mf], bf);
                        mma16(acc[mf][nfp + 1], af[mf], bf + 2);
                    }
                }
            }
        }
    }
};

__device__ __forceinline__ void gemm_init(GemmCore& gc, const __half* A,
                                          const __half* Wt, int K, int bm,
                                          int bn, uint32_t smBase)
{
    const int tid = threadIdx.x, lane = tid & 31;
    gc.smBase = smBase; gc.A = A; gc.Wt = Wt; gc.K = K;
    gc.bm = bm; gc.bn = bn; gc.tid = tid;
    gc.wm = (tid >> 5) >> 2; gc.wn = (tid >> 5) & 3;
    gc.rselA = (lane & 7) + ((lane >> 3) & 1) * 8;
    gc.cselA = ((lane >> 4) & 1) * 16;
    gc.rselB = (lane & 7) + ((lane >> 4) & 1) * 8;
    gc.cselB = ((lane >> 3) & 1) * 16;
}

// ---------------------------------------------------------------------------
// Fused Q + KV projection. grid (12, 64): bx 0-7 -> Q tiles, 8-11 -> KV.
// ---------------------------------------------------------------------------
__global__ __launch_bounds__(256, 2)
void tcmm_qkv(const __half* __restrict__ A, const __half* __restrict__ wqt,
              const __half* __restrict__ wkvt,
              const float* __restrict__ cosb, const float* __restrict__ sinb)
{
    extern __shared__ __align__(16) uint32_t gsm[];
    const bool isQ = blockIdx.x < 8;
    const int  bn  = (isQ ? blockIdx.x : blockIdx.x - 8) * 128;
    const int  bm  = blockIdx.y * 128;

    GemmCore gc;
    gemm_init(gc, A, isQ ? wqt : wkvt, DM, bm, bn, smem_u32(gsm));

    float acc[4][4][4] = {};
    gc.run(acc);

    const int lane = threadIdx.x & 31, g = lane >> 2, t = lane & 3;
    const int wid  = threadIdx.x >> 5, wm = wid >> 2, wn = wid & 3;

#pragma unroll
    for (int mf = 0; mf < 4; mf++) {
#pragma unroll
        for (int half = 0; half < 2; half++) {
            const int r  = bm + wm * 64 + mf * 16 + g + half * 8;
            const int bq = r >> 11, tq = r & (TT - 1);
#pragma unroll
            for (int nf = 0; nf < 4; nf++) {
                const float v0 = acc[mf][nf][half * 2];
                const float v1 = acc[mf][nf][half * 2 + 1];
                const int col = bn + wn * 32 + nf * 8 + 2 * t;
                if (isQ) {
                    const int h = col >> 6, d = col & 63;
                    const float c  = cosb[tq * HD + d];
                    const float sn = sinb[tq * HD + d];
                    uint32_t p = packh2((v0 * c - v1 * sn) * SCQ,
                                        (v1 * c + v0 * sn) * SCQ);
                    *(uint32_t*)&g_qh[(((size_t)(bq * HQ + h) * TT + tq) << 6) + d] = p;
                } else {
                    const int hk = col >> 7, pair = (col >> 6) & 1, d = col & 63;
                    if (pair == 0) {
                        const float c  = cosb[tq * HD + d];
                        const float sn = sinb[tq * HD + d];
                        uint32_t p = packh2(v0 * c - v1 * sn, v1 * c + v0 * sn);
                        *(uint32_t*)&g_kh[(((size_t)(bq * HKV + hk) * TT + tq) << 6) + d] = p;
                    } else {
                        __half* dst = &g_vth[((size_t)(bq * HKV + hk) * HD + d) * TT + tq];
                        dst[0]  = __float2half(v0);
                        dst[TT] = __float2half(v1);
                    }
                }
            }
        }
    }
}

// ---------------------------------------------------------------------------
// Output projection: C = Ao @ Wo, plain fp32 store.
// ---------------------------------------------------------------------------
__global__ __launch_bounds__(256, 2)
void tcmm_o(const __half* __restrict__ A, const __half* __restrict__ Wt,
            float* __restrict__ C)
{
    extern __shared__ __align__(16) uint32_t gsm[];
    const int bm = blockIdx.y * 128, bn = blockIdx.x * 128;

    GemmCore gc;
    gemm_init(gc, A, Wt, DM, bm, bn, smem_u32(gsm));

    float acc[4][4][4] = {};
    gc.run(acc);

    const int lane = threadIdx.x & 31, g = lane >> 2, t = lane & 3;
    const int wid  = threadIdx.x >> 5, wm = wid >> 2, wn = wid & 3;

#pragma unroll
    for (int mf = 0; mf < 4; mf++)
#pragma unroll
        for (int half = 0; half < 2; half++) {
            const int r = bm + wm * 64 + mf * 16 + g + half * 8;
#pragma unroll
            for (int nf = 0; nf < 4; nf++) {
                const int col = bn + wn * 32 + nf * 8 + 2 * t;
                float2 o = {acc[mf][nf][half * 2], acc[mf][nf][half * 2 + 1]};
                *(float2*)(C + (size_t)r * DM + col) = o;
            }
        }
}

// ---------------------------------------------------------------------------
// Flash attention v3: 128 threads (4 warps), mf=2 per warp (32 q-rows),
// 128 q-rows/CTA, 2 CTAs/SM (regs ~222 x 128 thr = 28.4K).
// B fragments feed 4 MMAs each (halved smem reads). K-tile 64,
// 3-stage cp.async, P in registers. grid (BB*HQ, TT/128) = (64, 16).
// ---------------------------------------------------------------------------
#define AST 36
#define KTW (64 * AST)                  // words per K-or-V tile stage
#define ATTN_SMEM ((6 * KTW) * 4)       // 3 stages x (K,V)

__global__ __launch_bounds__(128, 2)
void attn_mma()
{
    extern __shared__ __align__(16) uint32_t dsm[];

    const int tid = threadIdx.x, lane = tid & 31, g = lane >> 2, t = lane & 3;
    const int bh  = blockIdx.x, b = bh >> 4, h = bh & 15, hk = h >> 2;
    const int qt  = blockIdx.y * 128;
    const int w   = tid >> 5;            // 0..3
    const int r0  = w * 32 + g;          // mf=0 base row; mf=1 adds 16

    const int rselB = (lane & 7) + ((lane >> 4) & 1) * 8;
    const int cselB = ((lane >> 3) & 1) * 16;

    const __half* Qb = g_qh  + (((size_t)bh * TT + qt) << 6);
    const __half* Kb = g_kh  + (((size_t)(b * HKV + hk) * TT) << 6);
    const __half* Vb = g_vth + ((size_t)(b * HKV + hk) * HD) * TT;

    // Q fragments for both mf halves (pre-scaled fp16 pairs)
    uint32_t qf[2][4][4];
#pragma unroll
    for (int mf = 0; mf < 2; mf++) {
        const int rr = r0 + mf * 16;
#pragma unroll
        for (int ks = 0; ks < 4; ks++) {
            qf[mf][ks][0] = *(const uint32_t*)(Qb + (size_t)rr * 64 + (ks * 8 + t) * 2);
            qf[mf][ks][1] = *(const uint32_t*)(Qb + (size_t)(rr + 8) * 64 + (ks * 8 + t) * 2);
            qf[mf][ks][2] = *(const uint32_t*)(Qb + (size_t)rr * 64 + (ks * 8 + t + 4) * 2);
            qf[mf][ks][3] = *(const uint32_t*)(Qb + (size_t)(rr + 8) * 64 + (ks * 8 + t + 4) * 2);
        }
    }

    const uint32_t smBase = smem_u32(dsm);

    auto load_tile = [&](int kt, int st) {
        const uint32_t kb = smBase + st * 2 * KTW * 4;
        const uint32_t vb = kb + KTW * 4;
#pragma unroll
        for (int i = 0; i < 4; i++) {
            int c = tid + i * 128;           // 0..511
            int rr = c >> 3, off = c & 7;
            cpa16(kb + rr * (AST * 4) + off * 16,
                  Kb + (size_t)(kt + rr) * 64 + off * 8);
            cpa16(vb + rr * (AST * 4) + off * 16,
                  Vb + (size_t)rr * TT + kt + off * 8);
        }
    };

    float o[2][8][4] = {};
    float m0[2] = {-3.0e38f, -3.0e38f}, m1[2] = {-3.0e38f, -3.0e38f};
    float l0[2] = {0.f, 0.f},           l1[2] = {0.f, 0.f};

    load_tile(0, 0);  CP_COMMIT();
    load_tile(64, 1); CP_COMMIT();

    const int NIT = TT / 64;
    for (int it = 0; it < NIT; it++) {
        if (it + 1 < NIT) CP_WAIT1(); else CP_WAIT0();
        __syncthreads();
        if (it + 2 < NIT) { load_tile((it + 2) * 64, (it + 2) % 3); CP_COMMIT(); }

        const int cur = it % 3;
        const uint32_t smKc = smBase + cur * 2 * KTW * 4;
        const uint32_t smVc = smKc + KTW * 4;

        // S = Q @ K^T for both mf halves (B fragment reused 4x)
        float s[2][8][4] = {};
#pragma unroll
        for (int nfp = 0; nfp < 8; nfp += 2) {
            const uint32_t ka = smKc + (nfp * 8 + rselB) * (AST * 4) + cselB;
#pragma unroll
            for (int ks = 0; ks < 4; ks++) {
                uint32_t bf[4];
                ldm4(bf, ka + ks * 32);
                mma16(s[0][nfp],     qf[0][ks], bf);
                mma16(s[0][nfp + 1], qf[0][ks], bf + 2);
                mma16(s[1][nfp],     qf[1][ks], bf);
                mma16(s[1][nfp + 1], qf[1][ks], bf + 2);
            }
        }

        // online softmax + P fragments, per mf half
        uint32_t af[2][4][4];
        float c0[2], c1[2];
#pragma unroll
        for (int mf = 0; mf < 2; mf++) {
            float tm0 = -3.0e38f, tm1 = -3.0e38f;
#pragma unroll
            for (int nf = 0; nf < 8; nf++) {
                tm0 = fmaxf(tm0, fmaxf(s[mf][nf][0], s[mf][nf][1]));
                tm1 = fmaxf(tm1, fmaxf(s[mf][nf][2], s[mf][nf][3]));
            }
            tm0 = fmaxf(tm0, __shfl_xor_sync(0xffffffffu, tm0, 1));
            tm0 = fmaxf(tm0, __shfl_xor_sync(0xffffffffu, tm0, 2));
            tm1 = fmaxf(tm1, __shfl_xor_sync(0xffffffffu, tm1, 1));
            tm1 = fmaxf(tm1, __shfl_xor_sync(0xffffffffu, tm1, 2));

            const float nm0 = fmaxf(m0[mf], tm0), nm1 = fmaxf(m1[mf], tm1);
            c0[mf] = ex2(m0[mf] - nm0);
            c1[mf] = ex2(m1[mf] - nm1);
            m0[mf] = nm0; m1[mf] = nm1;

            float lp0 = 0.f, lp1 = 0.f;
#pragma unroll
            for (int ks = 0; ks < 4; ks++) {
                const int lo = 2 * ks, hi = 2 * ks + 1;
                af[mf][ks][0] = ex2h2(packh2(s[mf][lo][0] - nm0, s[mf][lo][1] - nm0));
                af[mf][ks][1] = ex2h2(packh2(s[mf][lo][2] - nm1, s[mf][lo][3] - nm1));
                af[mf][ks][2] = ex2h2(packh2(s[mf][hi][0] - nm0, s[mf][hi][1] - nm0));
                af[mf][ks][3] = ex2h2(packh2(s[mf][hi][2] - nm1, s[mf][hi][3] - nm1));
                float2 f;
                f = __half22float2(*(__half2*)&af[mf][ks][0]); lp0 += f.x + f.y;
                f = __half22float2(*(__half2*)&af[mf][ks][2]); lp0 += f.x + f.y;
                f = __half22float2(*(__half2*)&af[mf][ks][1]); lp1 += f.x + f.y;
                f = __half22float2(*(__half2*)&af[mf][ks][3]); lp1 += f.x + f.y;
            }
            lp0 += __shfl_xor_sync(0xffffffffu, lp0, 1);
            lp0 += __shfl_xor_sync(0xffffffffu, lp0, 2);
            lp1 += __shfl_xor_sync(0xffffffffu, lp1, 1);
            lp1 += __shfl_xor_sync(0xffffffffu, lp1, 2);
            l0[mf] = l0[mf] * c0[mf] + lp0;
            l1[mf] = l1[mf] * c1[mf] + lp1;

#pragma unroll
            for (int nf = 0; nf < 8; nf++) {
                o[mf][nf][0] *= c0[mf]; o[mf][nf][1] *= c0[mf];
                o[mf][nf][2] *= c1[mf]; o[mf][nf][3] *= c1[mf];
            }
        }

        // O += P @ V (B fragment reused 4x)
#pragma unroll
        for (int nfp = 0; nfp < 8; nfp += 2) {
            const uint32_t va = smVc + (nfp * 8 + rselB) * (AST * 4) + cselB;
#pragma unroll
            for (int ks = 0; ks < 4; ks++) {
                uint32_t bf[4];
                ldm4(bf, va + ks * 32);
                mma16(o[0][nfp],     af[0][ks], bf);
                mma16(o[0][nfp + 1], af[0][ks], bf + 2);
                mma16(o[1][nfp],     af[1][ks], bf);
                mma16(o[1][nfp + 1], af[1][ks], bf + 2);
            }
        }
    }

#pragma unroll
    for (int mf = 0; mf < 2; mf++) {
        const float i0 = 1.f / l0[mf], i1 = 1.f / l1[mf];
        const int tr = qt + r0 + mf * 16;
#pragma unroll
        for (int nf = 0; nf < 8; nf++) {
            const int d = nf * 8 + 2 * t;
            *(uint32_t*)&g_aoh[((size_t)(b * TT + tr)     * DM) + h * 64 + d] =
                packh2(o[mf][nf][0] * i0, o[mf][nf][1] * i0);
            *(uint32_t*)&g_aoh[((size_t)(b * TT + tr + 8) * DM) + h * 64 + d] =
                packh2(o[mf][nf][2] * i1, o[mf][nf][3] * i1);
        }
    }
}

// ---------------------------------------------------------------------------
extern "C" void kernel_launch(void* const* d_in, const int* in_sizes, int n_in,
                              void* d_out, int out_size)
{
    const float* x    = (const float*)d_in[0];
    const float* cosb = (const float*)d_in[1];
    const float* sinb = (const float*)d_in[2];
    const float* Wq   = (const float*)d_in[3];
    const float* Wkv  = (const float*)d_in[4];
    const float* Wo   = (const float*)d_in[5];
    float* out = (float*)d_out;

    __half *p_xh = nullptr, *p_wqt = nullptr, *p_wkvt = nullptr,
           *p_wot = nullptr, *p_aoh = nullptr;
    cudaGetSymbolAddress((void**)&p_xh,  g_xh);
    cudaGetSymbolAddress((void**)&p_wqt, g_wqt);
    cudaGetSymbolAddress((void**)&p_wkvt,g_wkvt);
    cudaGetSymbolAddress((void**)&p_wot, g_wot);
    cudaGetSymbolAddress((void**)&p_aoh, g_aoh);

    cudaFuncSetAttribute(attn_mma, cudaFuncAttributeMaxDynamicSharedMemorySize,
                         ATTN_SMEM);
    cudaFuncSetAttribute(tcmm_qkv, cudaFuncAttributeMaxDynamicSharedMemorySize,
                         GEMM_SMEM);
    cudaFuncSetAttribute(tcmm_o, cudaFuncAttributeMaxDynamicSharedMemorySize,
                         GEMM_SMEM);

    // Prep: x -> fp16; all W -> transposed fp16 (single launch)
    cvt_fp16<<<(MROWS * DM) / (256 * 4), 256>>>(x, p_xh, MROWS * DM);
    {
        dim3 grid(DM / 32, DM / 32, 3), blk(32, 8);
        trW3<<<grid, blk>>>(Wq, Wkv, Wo, p_wqt, p_wkvt, p_wot);
    }

    {   // fused Q + KV projection (+RoPE, split, V transpose)
        dim3 grid(12, MROWS / 128);
        tcmm_qkv<<<grid, 256, GEMM_SMEM>>>(p_xh, p_wqt, p_wkvt, cosb, sinb);
    }
    {   // attention (128 q-rows per 128-thread CTA, 2 CTAs/SM)
        dim3 grid(BB * HQ, TT / 128);
        attn_mma<<<grid, 128, ATTN_SMEM>>>();
    }
    {   // output projection
        dim3 grid(DM / 128, MROWS / 128);
        tcmm_o<<<grid, 256, GEMM_SMEM>>>(p_aoh, p_wot, out);
    }
}

// round 13
// speedup vs baseline: 1.1236x; 1.0382x over previous
#include <cuda_runtime.h>
#include <cuda_fp16.h>
#include <cstdint>

#define BB    4
#define TT    2048
#define DM    1024
#define HQ    16
#define HKV   4
#define HD    64
#define MROWS (BB*TT)

#define SCQ 0.1803368801111204f         // 0.125 * log2(e)

// fp16 scratch (device globals)
__device__ __half g_xh  [MROWS*DM];
__device__ __half g_wqt [DM*DM];            // Wq^T  [n][k]
__device__ __half g_wkvt[(2*HKV*HD)*DM];    // Wkv^T [n][k]
__device__ __half g_wot [DM*DM];            // Wo^T  [n][k]
__device__ __half g_qh  [BB*HQ *TT*HD];     // (b*HQ+h, t, d), pre-scaled SCQ
__device__ __half g_kh  [BB*HKV*TT*HD];     // (b*HKV+hk, t, d)
__device__ __half g_vth [BB*HKV*HD*TT];     // (b*HKV+hk, d, t)
__device__ __half g_aoh [BB*TT*DM];         // (b, t, h*64+d)

// ---------------------------------------------------------------------------
__device__ __forceinline__ float ex2(float x) {
    float r; asm("ex2.approx.f32 %0, %1;" : "=f"(r) : "f"(x)); return r;
}
__device__ __forceinline__ uint32_t ex2h2(uint32_t x) {
    uint32_t r; asm("ex2.approx.f16x2 %0, %1;" : "=r"(r) : "r"(x)); return r;
}
__device__ __forceinline__ uint32_t smem_u32(const void* p) {
    return (uint32_t)__cvta_generic_to_shared(p);
}
__device__ __forceinline__ void cpa16(uint32_t dst, const void* src) {
    asm volatile("cp.async.cg.shared.global [%0], [%1], 16;"
                 :: "r"(dst), "l"(src));
}
#define CP_COMMIT() asm volatile("cp.async.commit_group;" ::: "memory")
#define CP_WAIT1()  asm volatile("cp.async.wait_group 1;" ::: "memory")
#define CP_WAIT0()  asm volatile("cp.async.wait_group 0;" ::: "memory")

__device__ __forceinline__ void ldm4(uint32_t* r, uint32_t addr) {
    asm volatile("ldmatrix.sync.aligned.m8n8.x4.shared.b16 {%0,%1,%2,%3}, [%4];"
                 : "=r"(r[0]), "=r"(r[1]), "=r"(r[2]), "=r"(r[3]) : "r"(addr));
}
__device__ __forceinline__ void mma16(float* d, const uint32_t* a, const uint32_t* b) {
    asm volatile(
        "mma.sync.aligned.m16n8k16.row.col.f32.f16.f16.f32 "
        "{%0,%1,%2,%3}, {%4,%5,%6,%7}, {%8,%9}, {%0,%1,%2,%3};"
        : "+f"(d[0]), "+f"(d[1]), "+f"(d[2]), "+f"(d[3])
        : "r"(a[0]), "r"(a[1]), "r"(a[2]), "r"(a[3]), "r"(b[0]), "r"(b[1]));
}
__device__ __forceinline__ uint32_t packh2(float a, float b) {
    __half2 h = __floats2half2_rn(a, b);
    return *(uint32_t*)&h;
}

// ---------------------------------------------------------------------------
// Prep kernels
// ---------------------------------------------------------------------------
__global__ __launch_bounds__(256)
void cvt_fp16(const float* __restrict__ src, __half* __restrict__ dst, int n)
{
    int i = (blockIdx.x * 256 + threadIdx.x) * 4;
    if (i < n) {
        float4 v = *(const float4*)(src + i);
        uint2 o = {packh2(v.x, v.y), packh2(v.z, v.w)};
        *(uint2*)(dst + i) = o;
    }
}

// All three W transposes in one launch. blockIdx.z: 0=Wq, 1=Wkv, 2=Wo.
__global__ __launch_bounds__(256)
void trW3(const float* __restrict__ Wq, const float* __restrict__ Wkv,
          const float* __restrict__ Wo,
          __half* __restrict__ wqt, __half* __restrict__ wkvt,
          __half* __restrict__ wot)
{
    const float* W; __half* Wt; int N;
    if (blockIdx.z == 0)      { W = Wq;  Wt = wqt;  N = DM; }
    else if (blockIdx.z == 1) { W = Wkv; Wt = wkvt; N = 2 * HKV * HD; }
    else                      { W = Wo;  Wt = wot;  N = DM; }
    const int n0 = blockIdx.x * 32;
    if (n0 >= N) return;
    const int k0 = blockIdx.y * 32;

    __shared__ float tile[32][33];
#pragma unroll
    for (int i = threadIdx.y; i < 32; i += 8)
        tile[i][threadIdx.x] = W[(size_t)(k0 + i) * N + n0 + threadIdx.x];
    __syncthreads();
#pragma unroll
    for (int i = threadIdx.y; i < 32; i += 8)
        Wt[(size_t)(n0 + i) * DM + k0 + threadIdx.x] =
            __float2half(tile[threadIdx.x][i]);
}

// ---------------------------------------------------------------------------
// GEMM core: 128x128 tile, BK=64, 256 thr, 2(M)x4(N) warps, ldmatrix,
// 3-stage cp.async pipeline (steady-state wait_group 1).
// ---------------------------------------------------------------------------
#define GST 36                               // words per smem row (64h + pad)
#define GTW (128 * GST)                      // words per A-or-B tile stage
#define GEMM_SMEM ((6 * GTW) * 4)            // 3 stages x (A,B)

struct GemmCore {
    uint32_t smBase;
    const __half* A;
    const __half* Wt;
    int K, bm, bn, tid;
    int rselA, cselA, rselB, cselB, wm, wn;

    __device__ __forceinline__ void load_tile(int kt, int st) {
        const uint32_t ab = smBase + st * 2 * GTW * 4;
        const uint32_t bb = ab + GTW * 4;
#pragma unroll
        for (int i = 0; i < 4; i++) {
            int c = tid + i * 256;
            int rr = c >> 3, off = c & 7;
            cpa16(ab + rr * (GST * 4) + off * 16,
                  A + (size_t)(bm + rr) * K + kt + off * 8);
            cpa16(bb + rr * (GST * 4) + off * 16,
                  Wt + (size_t)(bn + rr) * K + kt + off * 8);
        }
    }

    __device__ __forceinline__ void run(float acc[4][4][4]) {
        load_tile(0, 0);  CP_COMMIT();
        load_tile(64, 1); CP_COMMIT();
        const int NIT = K / 64;
        for (int it = 0; it < NIT; it++) {
            if (it + 1 < NIT) CP_WAIT1(); else CP_WAIT0();
            __syncthreads();
            if (it + 2 < NIT) { load_tile((it + 2) * 64, (it + 2) % 3); CP_COMMIT(); }
            const int cur = it % 3;
            const uint32_t smAc = smBase + cur * 2 * GTW * 4;
            const uint32_t smBc = smAc + GTW * 4;
#pragma unroll
            for (int ks = 0; ks < 4; ks++) {
                uint32_t af[4][4];
#pragma unroll
                for (int mf = 0; mf < 4; mf++)
                    ldm4(af[mf], smAc + (wm * 64 + mf * 16 + rselA) * (GST * 4)
                                   + cselA + ks * 32);
#pragma unroll
                for (int nfp = 0; nfp < 4; nfp += 2) {
                    uint32_t bf[4];
                    ldm4(bf, smBc + (wn * 32 + nfp * 8 + rselB) * (GST * 4)
                               + cselB + ks * 32);
#pragma unroll
                    for (int mf = 0; mf < 4; mf++) {
                        mma16(acc[mf][nfp],     af[mf], bf);
                        mma16(acc[mf][nfp + 1], af[mf], bf + 2);
                    }
                }
            }
        }
    }
};

__device__ __forceinline__ void gemm_init(GemmCore& gc, const __half* A,
                                          const __half* Wt, int K, int bm,
                                          int bn, uint32_t smBase)
{
    const int tid = threadIdx.x, lane = tid & 31;
    gc.smBase = smBase; gc.A = A; gc.Wt = Wt; gc.K = K;
    gc.bm = bm; gc.bn = bn; gc.tid = tid;
    gc.wm = (tid >> 5) >> 2; gc.wn = (tid >> 5) & 3;
    gc.rselA = (lane & 7) + ((lane >> 3) & 1) * 8;
    gc.cselA = ((lane >> 4) & 1) * 16;
    gc.rselB = (lane & 7) + ((lane >> 4) & 1) * 8;
    gc.cselB = ((lane >> 3) & 1) * 16;
}

// ---------------------------------------------------------------------------
// Fused Q + KV projection. grid (12, 64): bx 0-7 -> Q tiles, 8-11 -> KV.
// ---------------------------------------------------------------------------
__global__ __launch_bounds__(256, 2)
void tcmm_qkv(const __half* __restrict__ A, const __half* __restrict__ wqt,
              const __half* __restrict__ wkvt,
              const float* __restrict__ cosb, const float* __restrict__ sinb)
{
    extern __shared__ __align__(16) uint32_t gsm[];
    const bool isQ = blockIdx.x < 8;
    const int  bn  = (isQ ? blockIdx.x : blockIdx.x - 8) * 128;
    const int  bm  = blockIdx.y * 128;

    GemmCore gc;
    gemm_init(gc, A, isQ ? wqt : wkvt, DM, bm, bn, smem_u32(gsm));

    float acc[4][4][4] = {};
    gc.run(acc);

    const int lane = threadIdx.x & 31, g = lane >> 2, t = lane & 3;
    const int wid  = threadIdx.x >> 5, wm = wid >> 2, wn = wid & 3;

#pragma unroll
    for (int mf = 0; mf < 4; mf++) {
#pragma unroll
        for (int half = 0; half < 2; half++) {
            const int r  = bm + wm * 64 + mf * 16 + g + half * 8;
            const int bq = r >> 11, tq = r & (TT - 1);
#pragma unroll
            for (int nf = 0; nf < 4; nf++) {
                const float v0 = acc[mf][nf][half * 2];
                const float v1 = acc[mf][nf][half * 2 + 1];
                const int col = bn + wn * 32 + nf * 8 + 2 * t;
                if (isQ) {
                    const int h = col >> 6, d = col & 63;
                    const float c  = cosb[tq * HD + d];
                    const float sn = sinb[tq * HD + d];
                    uint32_t p = packh2((v0 * c - v1 * sn) * SCQ,
                                        (v1 * c + v0 * sn) * SCQ);
                    *(uint32_t*)&g_qh[(((size_t)(bq * HQ + h) * TT + tq) << 6) + d] = p;
                } else {
                    const int hk = col >> 7, pair = (col >> 6) & 1, d = col & 63;
                    if (pair == 0) {
                        const float c  = cosb[tq * HD + d];
                        const float sn = sinb[tq * HD + d];
                        uint32_t p = packh2(v0 * c - v1 * sn, v1 * c + v0 * sn);
                        *(uint32_t*)&g_kh[(((size_t)(bq * HKV + hk) * TT + tq) << 6) + d] = p;
                    } else {
                        __half* dst = &g_vth[((size_t)(bq * HKV + hk) * HD + d) * TT + tq];
                        dst[0]  = __float2half(v0);
                        dst[TT] = __float2half(v1);
                    }
                }
            }
        }
    }
}

// ---------------------------------------------------------------------------
// Output projection: C = Ao @ Wo, plain fp32 store.
// ---------------------------------------------------------------------------
__global__ __launch_bounds__(256, 2)
void tcmm_o(const __half* __restrict__ A, const __half* __restrict__ Wt,
            float* __restrict__ C)
{
    extern __shared__ __align__(16) uint32_t gsm[];
    const int bm = blockIdx.y * 128, bn = blockIdx.x * 128;

    GemmCore gc;
    gemm_init(gc, A, Wt, DM, bm, bn, smem_u32(gsm));

    float acc[4][4][4] = {};
    gc.run(acc);

    const int lane = threadIdx.x & 31, g = lane >> 2, t = lane & 3;
    const int wid  = threadIdx.x >> 5, wm = wid >> 2, wn = wid & 3;

#pragma unroll
    for (int mf = 0; mf < 4; mf++)
#pragma unroll
        for (int half = 0; half < 2; half++) {
            const int r = bm + wm * 64 + mf * 16 + g + half * 8;
#pragma unroll
            for (int nf = 0; nf < 4; nf++) {
                const int col = bn + wn * 32 + nf * 8 + 2 * t;
                float2 o = {acc[mf][nf][half * 2], acc[mf][nf][half * 2 + 1]};
                *(float2*)(C + (size_t)r * DM + col) = o;
            }
        }
}

// ---------------------------------------------------------------------------
// Flash attention v4: 128 threads (4 warps), mf=2 (32 q-rows/warp),
// 128 q-rows/CTA, 2 CTAs/SM. V tile extended with ones-row (row 64) so the
// PV MMA also produces the softmax denominator l (no per-tile shfl/adds).
// K-tile 64, 3-stage cp.async. grid (BB*HQ, TT/128).
// ---------------------------------------------------------------------------
#define AST   36
#define KTWK  (64 * AST)                // K tile words
#define KTWV  (80 * AST)                // V tile words (64 data + 16 const rows)
#define STAGE (KTWK + KTWV)
#define ATTN_SMEM ((3 * STAGE) * 4)

__global__ __launch_bounds__(128, 2)
void attn_mma()
{
    extern __shared__ __align__(16) uint32_t dsm[];

    const int tid = threadIdx.x, lane = tid & 31, g = lane >> 2, t = lane & 3;
    const int bh  = blockIdx.x, b = bh >> 4, h = bh & 15, hk = h >> 2;
    const int qt  = blockIdx.y * 128;
    const int w   = tid >> 5;            // 0..3
    const int r0  = w * 32 + g;          // mf=0 base row; mf=1 adds 16

    const int rselB = (lane & 7) + ((lane >> 4) & 1) * 8;
    const int cselB = ((lane >> 3) & 1) * 16;

    const __half* Qb = g_qh  + (((size_t)bh * TT + qt) << 6);
    const __half* Kb = g_kh  + (((size_t)(b * HKV + hk) * TT) << 6);
    const __half* Vb = g_vth + ((size_t)(b * HKV + hk) * HD) * TT;

    // Init constant V rows (64..79) in all 3 stages: row 64 = 1.0, rest = 0.
    // These rows are never touched by cp.async loads.
#pragma unroll
    for (int st = 0; st < 3; st++) {
        uint32_t* vrows = dsm + st * STAGE + KTWK;
        for (int idx = tid; idx < 16 * 32; idx += 128) {
            const int rr = 64 + (idx >> 5), cw = idx & 31;
            vrows[rr * AST + cw] = (rr == 64) ? 0x3C003C00u : 0u;
        }
    }

    // Q fragments for both mf halves (pre-scaled fp16 pairs)
    uint32_t qf[2][4][4];
#pragma unroll
    for (int mf = 0; mf < 2; mf++) {
        const int rr = r0 + mf * 16;
#pragma unroll
        for (int ks = 0; ks < 4; ks++) {
            qf[mf][ks][0] = *(const uint32_t*)(Qb + (size_t)rr * 64 + (ks * 8 + t) * 2);
            qf[mf][ks][1] = *(const uint32_t*)(Qb + (size_t)(rr + 8) * 64 + (ks * 8 + t) * 2);
            qf[mf][ks][2] = *(const uint32_t*)(Qb + (size_t)rr * 64 + (ks * 8 + t + 4) * 2);
            qf[mf][ks][3] = *(const uint32_t*)(Qb + (size_t)(rr + 8) * 64 + (ks * 8 + t + 4) * 2);
        }
    }

    const uint32_t smBase = smem_u32(dsm);

    auto load_tile = [&](int kt, int st) {
        const uint32_t kb = smBase + st * STAGE * 4;
        const uint32_t vb = kb + KTWK * 4;
#pragma unroll
        for (int i = 0; i < 4; i++) {
            int c = tid + i * 128;           // 0..511
            int rr = c >> 3, off = c & 7;
            cpa16(kb + rr * (AST * 4) + off * 16,
                  Kb + (size_t)(kt + rr) * 64 + off * 8);
            cpa16(vb + rr * (AST * 4) + off * 16,
                  Vb + (size_t)rr * TT + kt + off * 8);
        }
    };

    float o[2][8][4] = {};
    float ol[2][4] = {};                 // l accumulators (from ones-row MMA)
    float m0[2] = {-3.0e38f, -3.0e38f}, m1[2] = {-3.0e38f, -3.0e38f};

    load_tile(0, 0);  CP_COMMIT();
    load_tile(64, 1); CP_COMMIT();

    const int NIT = TT / 64;
    for (int it = 0; it < NIT; it++) {
        if (it + 1 < NIT) CP_WAIT1(); else CP_WAIT0();
        __syncthreads();
        if (it + 2 < NIT) { load_tile((it + 2) * 64, (it + 2) % 3); CP_COMMIT(); }

        const int cur = it % 3;
        const uint32_t smKc = smBase + cur * STAGE * 4;
        const uint32_t smVc = smKc + KTWK * 4;

        // S = Q @ K^T for both mf halves (B fragment reused 4x)
        float s[2][8][4] = {};
#pragma unroll
        for (int nfp = 0; nfp < 8; nfp += 2) {
            const uint32_t ka = smKc + (nfp * 8 + rselB) * (AST * 4) + cselB;
#pragma unroll
            for (int ks = 0; ks < 4; ks++) {
                uint32_t bf[4];
                ldm4(bf, ka + ks * 32);
                mma16(s[0][nfp],     qf[0][ks], bf);
                mma16(s[0][nfp + 1], qf[0][ks], bf + 2);
                mma16(s[1][nfp],     qf[1][ks], bf);
                mma16(s[1][nfp + 1], qf[1][ks], bf + 2);
            }
        }

        // online softmax + P fragments, per mf half
        uint32_t af[2][4][4];
#pragma unroll
        for (int mf = 0; mf < 2; mf++) {
            float tm0 = -3.0e38f, tm1 = -3.0e38f;
#pragma unroll
            for (int nf = 0; nf < 8; nf++) {
                tm0 = fmaxf(tm0, fmaxf(s[mf][nf][0], s[mf][nf][1]));
                tm1 = fmaxf(tm1, fmaxf(s[mf][nf][2], s[mf][nf][3]));
            }
            tm0 = fmaxf(tm0, __shfl_xor_sync(0xffffffffu, tm0, 1));
            tm0 = fmaxf(tm0, __shfl_xor_sync(0xffffffffu, tm0, 2));
            tm1 = fmaxf(tm1, __shfl_xor_sync(0xffffffffu, tm1, 1));
            tm1 = fmaxf(tm1, __shfl_xor_sync(0xffffffffu, tm1, 2));

            const float nm0 = fmaxf(m0[mf], tm0), nm1 = fmaxf(m1[mf], tm1);
            const float c0 = ex2(m0[mf] - nm0);
            const float c1 = ex2(m1[mf] - nm1);
            m0[mf] = nm0; m1[mf] = nm1;

#pragma unroll
            for (int ks = 0; ks < 4; ks++) {
                const int lo = 2 * ks, hi = 2 * ks + 1;
                af[mf][ks][0] = ex2h2(packh2(s[mf][lo][0] - nm0, s[mf][lo][1] - nm0));
                af[mf][ks][1] = ex2h2(packh2(s[mf][lo][2] - nm1, s[mf][lo][3] - nm1));
                af[mf][ks][2] = ex2h2(packh2(s[mf][hi][0] - nm0, s[mf][hi][1] - nm0));
                af[mf][ks][3] = ex2h2(packh2(s[mf][hi][2] - nm1, s[mf][hi][3] - nm1));
            }

#pragma unroll
            for (int nf = 0; nf < 8; nf++) {
                o[mf][nf][0] *= c0; o[mf][nf][1] *= c0;
                o[mf][nf][2] *= c1; o[mf][nf][3] *= c1;
            }
            ol[mf][0] *= c0; ol[mf][1] *= c0;
            ol[mf][2] *= c1; ol[mf][3] *= c1;
        }

        // O += P @ V (B fragment reused 4x)
#pragma unroll
        for (int nfp = 0; nfp < 8; nfp += 2) {
            const uint32_t va = smVc + (nfp * 8 + rselB) * (AST * 4) + cselB;
#pragma unroll
            for (int ks = 0; ks < 4; ks++) {
                uint32_t bf[4];
                ldm4(bf, va + ks * 32);
                mma16(o[0][nfp],     af[0][ks], bf);
                mma16(o[0][nfp + 1], af[0][ks], bf + 2);
                mma16(o[1][nfp],     af[1][ks], bf);
                mma16(o[1][nfp + 1], af[1][ks], bf + 2);
            }
        }
        // l += P @ ones (rows 64..79 of V tile; only col 64 is ones)
        {
            const uint32_t la = smVc + (64 + rselB) * (AST * 4) + cselB;
#pragma unroll
            for (int ks = 0; ks < 4; ks++) {
                uint32_t bf[4];
                ldm4(bf, la + ks * 32);
                mma16(ol[0], af[0][ks], bf);
                mma16(ol[1], af[1][ks], bf);
            }
        }
    }

    // l lives in lane t=0 of each quad: ol[mf][0] (row g), ol[mf][2] (row g+8)
#pragma unroll
    for (int mf = 0; mf < 2; mf++) {
        const float lr0 = __shfl_sync(0xffffffffu, ol[mf][0], lane & 28);
        const float lr1 = __shfl_sync(0xffffffffu, ol[mf][2], lane & 28);
        const float i0 = 1.f / lr0, i1 = 1.f / lr1;
        const int tr = qt + r0 + mf * 16;
#pragma unroll
        for (int nf = 0; nf < 8; nf++) {
            const int d = nf * 8 + 2 * t;
            *(uint32_t*)&g_aoh[((size_t)(b * TT + tr)     * DM) + h * 64 + d] =
                packh2(o[mf][nf][0] * i0, o[mf][nf][1] * i0);
            *(uint32_t*)&g_aoh[((size_t)(b * TT + tr + 8) * DM) + h * 64 + d] =
                packh2(o[mf][nf][2] * i1, o[mf][nf][3] * i1);
        }
    }
}

// ---------------------------------------------------------------------------
extern "C" void kernel_launch(void* const* d_in, const int* in_sizes, int n_in,
                              void* d_out, int out_size)
{
    const float* x    = (const float*)d_in[0];
    const float* cosb = (const float*)d_in[1];
    const float* sinb = (const float*)d_in[2];
    const float* Wq   = (const float*)d_in[3];
    const float* Wkv  = (const float*)d_in[4];
    const float* Wo   = (const float*)d_in[5];
    float* out = (float*)d_out;

    __half *p_xh = nullptr, *p_wqt = nullptr, *p_wkvt = nullptr,
           *p_wot = nullptr, *p_aoh = nullptr;
    cudaGetSymbolAddress((void**)&p_xh,  g_xh);
    cudaGetSymbolAddress((void**)&p_wqt, g_wqt);
    cudaGetSymbolAddress((void**)&p_wkvt,g_wkvt);
    cudaGetSymbolAddress((void**)&p_wot, g_wot);
    cudaGetSymbolAddress((void**)&p_aoh, g_aoh);

    cudaFuncSetAttribute(attn_mma, cudaFuncAttributeMaxDynamicSharedMemorySize,
                         ATTN_SMEM);
    cudaFuncSetAttribute(tcmm_qkv, cudaFuncAttributeMaxDynamicSharedMemorySize,
                         GEMM_SMEM);
    cudaFuncSetAttribute(tcmm_o, cudaFuncAttributeMaxDynamicSharedMemorySize,
                         GEMM_SMEM);

    // Prep: x -> fp16; all W -> transposed fp16 (single launch)
    cvt_fp16<<<(MROWS * DM) / (256 * 4), 256>>>(x, p_xh, MROWS * DM);
    {
        dim3 grid(DM / 32, DM / 32, 3), blk(32, 8);
        trW3<<<grid, blk>>>(Wq, Wkv, Wo, p_wqt, p_wkvt, p_wot);
    }

    {   // fused Q + KV projection (+RoPE, split, V transpose)
        dim3 grid(12, MROWS / 128);
        tcmm_qkv<<<grid, 256, GEMM_SMEM>>>(p_xh, p_wqt, p_wkvt, cosb, sinb);
    }
    {   // attention (128 q-rows per 128-thread CTA, 2 CTAs/SM)
        dim3 grid(BB * HQ, TT / 128);
        attn_mma<<<grid, 128, ATTN_SMEM>>>();
    }
    {   // output projection
        dim3 grid(DM / 128, MROWS / 128);
        tcmm_o<<<grid, 256, GEMM_SMEM>>>(p_aoh, p_wot, out);
    }
}